// round 6
// baseline (speedup 1.0000x reference)
#include <cuda_runtime.h>
#include <cstdint>

#define NB 32
#define NS 512
#define NI 128
#define NH 128
#define NO 32
#define G3 384

typedef unsigned long long u64;

// ---------------- scratch (static device globals; no dynamic alloc) ----------
__device__ float  g_ih[(size_t)NS * NB * G3];       // ih[s][b][g]
__device__ float4 g_coef[(size_t)NS * NB * NH];     // {cR, cN, cZ, z} per (t,b,j)
__device__ float  g_WrT[NH * NH];                   // WrT[i][j] = W_hh[j][i]
__device__ float  g_WnT[NH * NH];                   // WnT[i][j] = W_hh[2H+j][i]
__device__ float  g_WzT[NH * NH];                   // WzT[i][j] = W_hh[H+j][i]

// ---------------- packed f32x2 helpers ---------------------------------------
__device__ __forceinline__ u64 pk2(float x, float y) {
    u64 r; asm("mov.b64 %0, {%1,%2};" : "=l"(r) : "f"(x), "f"(y)); return r;
}
__device__ __forceinline__ float2 up2(u64 v) {
    float2 r; asm("mov.b64 {%0,%1}, %2;" : "=f"(r.x), "=f"(r.y) : "l"(v)); return r;
}
__device__ __forceinline__ void fma2(u64 &d, u64 a, u64 b) {
    asm("fma.rn.f32x2 %0, %1, %2, %0;" : "+l"(d) : "l"(a), "l"(b));
}
__device__ __forceinline__ u64 mul2(u64 a, u64 b) {
    u64 d; asm("mul.rn.f32x2 %0, %1, %2;" : "=l"(d) : "l"(a), "l"(b)); return d;
}
// 16B shared load directly into two b64 regs (feeds FFMA2 without repack MOVs)
__device__ __forceinline__ void lds128(u64 &a, u64 &b, const void* p) {
    unsigned addr = (unsigned)__cvta_generic_to_shared(p);
    asm volatile("ld.shared.v2.b64 {%0,%1}, [%2];" : "=l"(a), "=l"(b) : "r"(addr));
}

__device__ __forceinline__ float sigm(float x) {
    return 1.f / (1.f + __expf(-x));
}
__device__ __forceinline__ float tanh_acc(float a) {
    float ac = fminf(fmaxf(a, -15.f), 15.f);
    float e2 = __expf(2.f * ac);
    return (e2 - 1.f) / (e2 + 1.f);
}

// ---------------- K0: transpose W_hh sub-blocks -------------------------------
__global__ void k_transpose(const float* __restrict__ W_hh) {
    int idx = blockIdx.x * blockDim.x + threadIdx.x;
    if (idx >= 3 * NH * NH) return;
    int m = idx / (NH * NH);
    int rem = idx - m * (NH * NH);
    int i = rem >> 7, j = rem & 127;
    int srcRow = (m == 0) ? j : ((m == 1) ? (2 * NH + j) : (NH + j));
    float v = W_hh[(size_t)srcRow * NH + i];
    if (m == 0)      g_WrT[rem] = v;
    else if (m == 1) g_WnT[rem] = v;
    else             g_WzT[rem] = v;
}

// ---------------- K1: ih = x @ W_ih^T + b_ih (W rows in registers) ------------
__global__ void __launch_bounds__(384, 1)
k_ih(const float* __restrict__ x, const float* __restrict__ W_ih,
     const float* __restrict__ b_ih) {
    __shared__ __align__(16) float sx[NI];
    int g = threadIdx.x;
    u64 w[64];
    const float2* wrow = (const float2*)(W_ih + (size_t)g * NI);
#pragma unroll
    for (int k = 0; k < 64; k++) { float2 v = wrow[k]; w[k] = pk2(v.x, v.y); }
    float bias = b_ih[g];

    for (int p = blockIdx.x; p < NS * NB; p += gridDim.x) {
        int s = p >> 5, b = p & 31;
        if (g < 32)
            ((float4*)sx)[g] = ((const float4*)(x + ((size_t)b * NS + s) * NI))[g];
        __syncthreads();
        u64 a0 = 0ull, a1 = 0ull, a2 = 0ull, a3 = 0ull;
#pragma unroll
        for (int k = 0; k < 16; k++) {
            u64 h0, h1, h2, h3;
            lds128(h0, h1, &sx[8 * k]);
            lds128(h2, h3, &sx[8 * k + 4]);
            fma2(a0, w[4 * k + 0], h0);
            fma2(a1, w[4 * k + 1], h1);
            fma2(a2, w[4 * k + 2], h2);
            fma2(a3, w[4 * k + 3], h3);
        }
        float2 f0 = up2(a0), f1 = up2(a1), f2 = up2(a2), f3 = up2(a3);
        float dot = ((f0.x + f0.y) + (f1.x + f1.y)) + ((f2.x + f2.y) + (f3.x + f3.y));
        g_ih[((size_t)s * NB + b) * G3 + g] = dot + bias;
        __syncthreads();
    }
}

// ---------------- K2: sequential GRU scan, one block per batch ----------------
__global__ void __launch_bounds__(384, 1)
k_scan(const float* __restrict__ W_hh, const float* __restrict__ b_hh,
       const float* __restrict__ W_y, const float* __restrict__ b_y,
       float* __restrict__ out) {
    __shared__ __align__(16) float sh_h[NH];
    __shared__ float sh_z[NH];
    __shared__ float sh_M[NH];
    __shared__ float sh_in[NH];
    int g = threadIdx.x;
    int b = blockIdx.x;

    u64 w[64];
    const float2* wrow = (const float2*)(W_hh + (size_t)g * NH);
#pragma unroll
    for (int k = 0; k < 64; k++) { float2 v = wrow[k]; w[k] = pk2(v.x, v.y); }
    float bias = b_hh[g];

    if (g < NH) sh_h[g] = 0.f;
    __syncthreads();

    const float* ihp = g_ih + (size_t)b * G3 + g;
    float4* coefp = g_coef + (size_t)b * NH;

    for (int t = 0; t < NS; t++) {
        float ihv = ihp[(size_t)t * NB * G3];   // L2 hit; hidden under GEMV
        u64 a0 = 0ull, a1 = 0ull, a2 = 0ull, a3 = 0ull;
#pragma unroll
        for (int k = 0; k < 16; k++) {
            u64 h0, h1, h2, h3;
            lds128(h0, h1, &sh_h[8 * k]);
            lds128(h2, h3, &sh_h[8 * k + 4]);
            fma2(a0, w[4 * k + 0], h0);
            fma2(a1, w[4 * k + 1], h1);
            fma2(a2, w[4 * k + 2], h2);
            fma2(a3, w[4 * k + 3], h3);
        }
        float2 f0 = up2(a0), f1 = up2(a1), f2 = up2(a2), f3 = up2(a3);
        float hh = ((f0.x + f0.y) + (f1.x + f1.y)) + ((f2.x + f2.y) + (f3.x + f3.y)) + bias;
        float pre = ihv + hh;

        float r_local = 0.f;
        if (g < NH) {
            r_local = sigm(pre);
        } else if (g < 2 * NH) {
            sh_z[g - NH] = sigm(pre);
        } else {
            sh_M[g - 2 * NH]  = hh;
            sh_in[g - 2 * NH] = ihv;
        }
        __syncthreads();

        if (g < NH) {
            float r = r_local;
            float z = sh_z[g];
            float M = sh_M[g];
            float n = tanh_acc(sh_in[g] + r * M);
            float hp = sh_h[g];
            float hn = (1.f - z) * n + z * hp;
            sh_h[g] = hn;
            float c67 = (1.f - n * n) * (1.f - z);
            float4 c;
            c.x = r * (1.f - r) * M * c67;   // scales WrT
            c.y = r * c67;                   // scales WnT
            c.z = z * (1.f - z) * (hp - n);  // scales WzT
            c.w = z;                         // diagonal
            coefp[(size_t)t * NB * NH + g] = c;
        }
        __syncthreads();
    }

    // y = h_last @ W_y^T + b_y
    if (g < NO) {
        const float* wy = W_y + (size_t)g * NH;
        float acc = b_y[g];
#pragma unroll 8
        for (int j = 0; j < NH; j++) acc += wy[j] * sh_h[j];
        out[(size_t)b * NO + g] = acc;
    }
}

// ---------------- K3: jacobian writer (HBM-write-bound) -----------------------
extern __shared__ float smem3[];
__global__ void __launch_bounds__(512, 1)
k_jac(float* __restrict__ out) {
    float*  sWr = smem3;
    float*  sWn = smem3 + 16384;
    float*  sWz = smem3 + 32768;
    float4* sC  = (float4*)(smem3 + 49152);
    int tid = threadIdx.x;
    for (int k = tid; k < NH * NH; k += 512) {
        sWr[k] = g_WrT[k];
        sWn[k] = g_WnT[k];
        sWz[k] = g_WzT[k];
    }
    int l = tid & 31, w = tid >> 5;   // warp handles 8 full rows -> coalesced STG.128

    for (int tile = blockIdx.x; tile < NS * NB; tile += gridDim.x) {
        __syncthreads();              // W visible (1st iter) + sC reg-loads done (later)
        if (tid < NH) sC[tid] = g_coef[(size_t)tile * NH + tid];
        __syncthreads();

        float4 c0 = sC[4 * l], c1 = sC[4 * l + 1], c2 = sC[4 * l + 2], c3 = sC[4 * l + 3];
        u64 cr01 = pk2(c0.x, c1.x), cr23 = pk2(c2.x, c3.x);
        u64 cn01 = pk2(c0.y, c1.y), cn23 = pk2(c2.y, c3.y);
        u64 cz01 = pk2(c0.z, c1.z), cz23 = pk2(c2.z, c3.z);
        float z0 = c0.w, z1 = c1.w, z2 = c2.w, z3 = c3.w;

        int t = tile >> 5, b = tile & 31;
        float* obase = out + 1024 + ((size_t)(NS - 1 - t) * NB + b) * (NH * NH);

#pragma unroll
        for (int ii = 0; ii < 8; ii++) {
            int i = w * 8 + ii;
            int idx = i * NH + 4 * l;
            u64 wr0, wr1, wn0, wn1, wz0, wz1;
            lds128(wr0, wr1, &sWr[idx]);
            lds128(wn0, wn1, &sWn[idx]);
            lds128(wz0, wz1, &sWz[idx]);
            u64 o01 = mul2(wr0, cr01); fma2(o01, wn0, cn01); fma2(o01, wz0, cz01);
            u64 o23 = mul2(wr1, cr23); fma2(o23, wn1, cn23); fma2(o23, wz1, cz23);
            if ((i >> 2) == l) {       // diagonal j == i lives in this lane
                int d = i & 3;
                if (d < 2) {
                    float2 p = up2(o01);
                    if (d == 0) p.x += z0; else p.y += z1;
                    o01 = pk2(p.x, p.y);
                } else {
                    float2 p = up2(o23);
                    if (d == 2) p.x += z2; else p.y += z3;
                    o23 = pk2(p.x, p.y);
                }
            }
            ulonglong2 st; st.x = o01; st.y = o23;
            *((ulonglong2*)(obase + idx)) = st;   // STG.128, 512B/row per warp
        }
    }
}

// ---------------- launcher ----------------------------------------------------
extern "C" void kernel_launch(void* const* d_in, const int* in_sizes, int n_in,
                              void* d_out, int out_size) {
    const float* x    = (const float*)d_in[0];
    const float* W_ih = (const float*)d_in[1];
    const float* W_hh = (const float*)d_in[2];
    const float* b_ih = (const float*)d_in[3];
    const float* b_hh = (const float*)d_in[4];
    const float* W_y  = (const float*)d_in[5];
    const float* b_y  = (const float*)d_in[6];
    float* out = (float*)d_out;

    (void)in_sizes; (void)n_in; (void)out_size;

    const int JAC_SMEM = (3 * NH * NH + 4 * NH) * (int)sizeof(float); // 198656 B
    cudaFuncSetAttribute(k_jac, cudaFuncAttributeMaxDynamicSharedMemorySize, JAC_SMEM);

    k_transpose<<<192, 256>>>(W_hh);
    k_ih<<<148, 384>>>(x, W_ih, b_ih);
    k_scan<<<NB, 384>>>(W_hh, b_hh, W_y, b_y, out);
    k_jac<<<148, 512, JAC_SMEM>>>(out);
}

// round 7
// speedup vs baseline: 1.0001x; 1.0001x over previous
#include <cuda_runtime.h>
#include <cstdint>

#define NB 32
#define NS 512
#define NI 128
#define NH 128
#define NO 32
#define G3 384

typedef unsigned long long u64;

// ---------------- scratch (static device globals; no dynamic alloc) ----------
__device__ float  g_ih[(size_t)NS * NB * G3];       // ih[s][b][g]
__device__ float4 g_coef[(size_t)NS * NB * NH];     // {cR, cN, cZ, z} per (t,b,j)
__device__ float  g_WrT[NH * NH];                   // WrT[i][j] = W_hh[j][i]
__device__ float  g_WnT[NH * NH];                   // WnT[i][j] = W_hh[2H+j][i]
__device__ float  g_WzT[NH * NH];                   // WzT[i][j] = W_hh[H+j][i]

// ---------------- packed f32x2 helpers ---------------------------------------
__device__ __forceinline__ u64 pk2(float x, float y) {
    u64 r; asm("mov.b64 %0, {%1,%2};" : "=l"(r) : "f"(x), "f"(y)); return r;
}
__device__ __forceinline__ float2 up2(u64 v) {
    float2 r; asm("mov.b64 {%0,%1}, %2;" : "=f"(r.x), "=f"(r.y) : "l"(v)); return r;
}
__device__ __forceinline__ void fma2(u64 &d, u64 a, u64 b) {
    asm("fma.rn.f32x2 %0, %1, %2, %0;" : "+l"(d) : "l"(a), "l"(b));
}
__device__ __forceinline__ u64 mul2(u64 a, u64 b) {
    u64 d; asm("mul.rn.f32x2 %0, %1, %2;" : "=l"(d) : "l"(a), "l"(b)); return d;
}
// 16B shared load directly into two b64 regs (feeds FFMA2 without repack MOVs)
__device__ __forceinline__ void lds128(u64 &a, u64 &b, const void* p) {
    unsigned addr = (unsigned)__cvta_generic_to_shared(p);
    asm volatile("ld.shared.v2.b64 {%0,%1}, [%2];" : "=l"(a), "=l"(b) : "r"(addr));
}

__device__ __forceinline__ float sigm(float x) {
    return 1.f / (1.f + __expf(-x));
}
__device__ __forceinline__ float tanh_acc(float a) {
    float ac = fminf(fmaxf(a, -15.f), 15.f);
    float e2 = __expf(2.f * ac);
    return (e2 - 1.f) / (e2 + 1.f);
}

// ---------------- K0: transpose W_hh sub-blocks -------------------------------
__global__ void k_transpose(const float* __restrict__ W_hh) {
    int idx = blockIdx.x * blockDim.x + threadIdx.x;
    if (idx >= 3 * NH * NH) return;
    int m = idx / (NH * NH);
    int rem = idx - m * (NH * NH);
    int i = rem >> 7, j = rem & 127;
    int srcRow = (m == 0) ? j : ((m == 1) ? (2 * NH + j) : (NH + j));
    float v = W_hh[(size_t)srcRow * NH + i];
    if (m == 0)      g_WrT[rem] = v;
    else if (m == 1) g_WnT[rem] = v;
    else             g_WzT[rem] = v;
}

// ---------------- K1: ih = x @ W_ih^T + b_ih (W rows in registers) ------------
__global__ void __launch_bounds__(384, 1)
k_ih(const float* __restrict__ x, const float* __restrict__ W_ih,
     const float* __restrict__ b_ih) {
    __shared__ __align__(16) float sx[NI];
    int g = threadIdx.x;
    u64 w[64];
    const float2* wrow = (const float2*)(W_ih + (size_t)g * NI);
#pragma unroll
    for (int k = 0; k < 64; k++) { float2 v = wrow[k]; w[k] = pk2(v.x, v.y); }
    float bias = b_ih[g];

    for (int p = blockIdx.x; p < NS * NB; p += gridDim.x) {
        int s = p >> 5, b = p & 31;
        if (g < 32)
            ((float4*)sx)[g] = ((const float4*)(x + ((size_t)b * NS + s) * NI))[g];
        __syncthreads();
        u64 a0 = 0ull, a1 = 0ull, a2 = 0ull, a3 = 0ull;
#pragma unroll
        for (int k = 0; k < 16; k++) {
            u64 h0, h1, h2, h3;
            lds128(h0, h1, &sx[8 * k]);
            lds128(h2, h3, &sx[8 * k + 4]);
            fma2(a0, w[4 * k + 0], h0);
            fma2(a1, w[4 * k + 1], h1);
            fma2(a2, w[4 * k + 2], h2);
            fma2(a3, w[4 * k + 3], h3);
        }
        float2 f0 = up2(a0), f1 = up2(a1), f2 = up2(a2), f3 = up2(a3);
        float dot = ((f0.x + f0.y) + (f1.x + f1.y)) + ((f2.x + f2.y) + (f3.x + f3.y));
        g_ih[((size_t)s * NB + b) * G3 + g] = dot + bias;
        __syncthreads();
    }
}

// ---------------- K2: sequential GRU scan, one block per batch ----------------
__global__ void __launch_bounds__(384, 1)
k_scan(const float* __restrict__ W_hh, const float* __restrict__ b_hh,
       const float* __restrict__ W_y, const float* __restrict__ b_y,
       float* __restrict__ out) {
    __shared__ __align__(16) float sh_h[NH];
    __shared__ float sh_z[NH];
    __shared__ float sh_M[NH];
    __shared__ float sh_in[NH];
    int g = threadIdx.x;
    int b = blockIdx.x;

    u64 w[64];
    const float2* wrow = (const float2*)(W_hh + (size_t)g * NH);
#pragma unroll
    for (int k = 0; k < 64; k++) { float2 v = wrow[k]; w[k] = pk2(v.x, v.y); }
    float bias = b_hh[g];

    if (g < NH) sh_h[g] = 0.f;
    __syncthreads();

    const float* ihp = g_ih + (size_t)b * G3 + g;
    float4* coefp = g_coef + (size_t)b * NH;

    for (int t = 0; t < NS; t++) {
        float ihv = ihp[(size_t)t * NB * G3];   // L2 hit; hidden under GEMV
        u64 a0 = 0ull, a1 = 0ull, a2 = 0ull, a3 = 0ull;
#pragma unroll
        for (int k = 0; k < 16; k++) {
            u64 h0, h1, h2, h3;
            lds128(h0, h1, &sh_h[8 * k]);
            lds128(h2, h3, &sh_h[8 * k + 4]);
            fma2(a0, w[4 * k + 0], h0);
            fma2(a1, w[4 * k + 1], h1);
            fma2(a2, w[4 * k + 2], h2);
            fma2(a3, w[4 * k + 3], h3);
        }
        float2 f0 = up2(a0), f1 = up2(a1), f2 = up2(a2), f3 = up2(a3);
        float hh = ((f0.x + f0.y) + (f1.x + f1.y)) + ((f2.x + f2.y) + (f3.x + f3.y)) + bias;
        float pre = ihv + hh;

        float r_local = 0.f;
        if (g < NH) {
            r_local = sigm(pre);
        } else if (g < 2 * NH) {
            sh_z[g - NH] = sigm(pre);
        } else {
            sh_M[g - 2 * NH]  = hh;
            sh_in[g - 2 * NH] = ihv;
        }
        __syncthreads();

        if (g < NH) {
            float r = r_local;
            float z = sh_z[g];
            float M = sh_M[g];
            float n = tanh_acc(sh_in[g] + r * M);
            float hp = sh_h[g];
            float hn = (1.f - z) * n + z * hp;
            sh_h[g] = hn;
            float c67 = (1.f - n * n) * (1.f - z);
            float4 c;
            c.x = r * (1.f - r) * M * c67;   // scales WrT
            c.y = r * c67;                   // scales WnT
            c.z = z * (1.f - z) * (hp - n);  // scales WzT
            c.w = z;                         // diagonal
            coefp[(size_t)t * NB * NH + g] = c;
        }
        __syncthreads();
    }

    // y = h_last @ W_y^T + b_y
    if (g < NO) {
        const float* wy = W_y + (size_t)g * NH;
        float acc = b_y[g];
#pragma unroll 8
        for (int j = 0; j < NH; j++) acc += wy[j] * sh_h[j];
        out[(size_t)b * NO + g] = acc;
    }
}

// ---------------- K3: jacobian writer (HBM-write-bound) -----------------------
extern __shared__ float smem3[];
__global__ void __launch_bounds__(512, 1)
k_jac(float* __restrict__ out) {
    float*  sWr = smem3;
    float*  sWn = smem3 + 16384;
    float*  sWz = smem3 + 32768;
    float4* sC  = (float4*)(smem3 + 49152);
    int tid = threadIdx.x;
    for (int k = tid; k < NH * NH; k += 512) {
        sWr[k] = g_WrT[k];
        sWn[k] = g_WnT[k];
        sWz[k] = g_WzT[k];
    }
    int l = tid & 31, w = tid >> 5;   // warp handles 8 full rows -> coalesced STG.128

    for (int tile = blockIdx.x; tile < NS * NB; tile += gridDim.x) {
        __syncthreads();              // W visible (1st iter) + sC reg-loads done (later)
        if (tid < NH) sC[tid] = g_coef[(size_t)tile * NH + tid];
        __syncthreads();

        float4 c0 = sC[4 * l], c1 = sC[4 * l + 1], c2 = sC[4 * l + 2], c3 = sC[4 * l + 3];
        u64 cr01 = pk2(c0.x, c1.x), cr23 = pk2(c2.x, c3.x);
        u64 cn01 = pk2(c0.y, c1.y), cn23 = pk2(c2.y, c3.y);
        u64 cz01 = pk2(c0.z, c1.z), cz23 = pk2(c2.z, c3.z);
        float z0 = c0.w, z1 = c1.w, z2 = c2.w, z3 = c3.w;

        int t = tile >> 5, b = tile & 31;
        float* obase = out + 1024 + ((size_t)(NS - 1 - t) * NB + b) * (NH * NH);

#pragma unroll
        for (int ii = 0; ii < 8; ii++) {
            int i = w * 8 + ii;
            int idx = i * NH + 4 * l;
            u64 wr0, wr1, wn0, wn1, wz0, wz1;
            lds128(wr0, wr1, &sWr[idx]);
            lds128(wn0, wn1, &sWn[idx]);
            lds128(wz0, wz1, &sWz[idx]);
            u64 o01 = mul2(wr0, cr01); fma2(o01, wn0, cn01); fma2(o01, wz0, cz01);
            u64 o23 = mul2(wr1, cr23); fma2(o23, wn1, cn23); fma2(o23, wz1, cz23);
            if ((i >> 2) == l) {       // diagonal j == i lives in this lane
                int d = i & 3;
                if (d < 2) {
                    float2 p = up2(o01);
                    if (d == 0) p.x += z0; else p.y += z1;
                    o01 = pk2(p.x, p.y);
                } else {
                    float2 p = up2(o23);
                    if (d == 2) p.x += z2; else p.y += z3;
                    o23 = pk2(p.x, p.y);
                }
            }
            ulonglong2 st; st.x = o01; st.y = o23;
            *((ulonglong2*)(obase + idx)) = st;   // STG.128, 512B/row per warp
        }
    }
}

// ---------------- launcher ----------------------------------------------------
extern "C" void kernel_launch(void* const* d_in, const int* in_sizes, int n_in,
                              void* d_out, int out_size) {
    const float* x    = (const float*)d_in[0];
    const float* W_ih = (const float*)d_in[1];
    const float* W_hh = (const float*)d_in[2];
    const float* b_ih = (const float*)d_in[3];
    const float* b_hh = (const float*)d_in[4];
    const float* W_y  = (const float*)d_in[5];
    const float* b_y  = (const float*)d_in[6];
    float* out = (float*)d_out;

    (void)in_sizes; (void)n_in; (void)out_size;

    const int JAC_SMEM = (3 * NH * NH + 4 * NH) * (int)sizeof(float); // 198656 B
    cudaFuncSetAttribute(k_jac, cudaFuncAttributeMaxDynamicSharedMemorySize, JAC_SMEM);

    k_transpose<<<192, 256>>>(W_hh);
    k_ih<<<148, 384>>>(x, W_ih, b_ih);
    k_scan<<<NB, 384>>>(W_hh, b_hh, W_y, b_y, out);
    k_jac<<<148, 512, JAC_SMEM>>>(out);
}